// round 1
// baseline (speedup 1.0000x reference)
#include <cuda_runtime.h>

// Problem constants
#define B_     16384
#define H_     128
#define G_     1100
#define SW_    2
#define NN_    1106      // G + 3*SW
#define GATES_ 640       // 5*H
#define KNB_   25        // (2*SW+1)^2

// ---------------- scratch (device globals; no allocation allowed) -----------
__device__ float g_gates[(size_t)B_ * GATES_];     // 40 MB  [B,640]
__device__ float g_combined[(size_t)B_ * 2 * H_];  // 16 MB  [B,256] = [mix | cy_h]
__device__ float g_atten[(size_t)B_ * H_];         // 8 MB   [B,128]
__device__ int   g_owner[NN_ * NN_];               // 4.9 MB last-writer map

__device__ __forceinline__ float sigmoidf_(float v) {
    return 1.0f / (1.0f + __expf(-v));
}

// ---------------- owner map (deterministic duplicate-scatter resolution) ----
__global__ void reset_owner_k() {
    int i = blockIdx.x * blockDim.x + threadIdx.x;
    if (i < NN_ * NN_) g_owner[i] = -1;
}

__global__ void owner_k(const int* __restrict__ gi) {
    int b = blockIdx.x * blockDim.x + threadIdx.x;
    int gx = gi[2 * b] + SW_;
    int gy = gi[2 * b + 1] + SW_;
    atomicMax(&g_owner[gx * NN_ + gy], b);
}

// ---------------- bulk memory copy (mem_new starts as memory) ---------------
__global__ void copy_mem_k(const float4* __restrict__ src, float4* __restrict__ dst) {
    size_t n = (size_t)NN_ * NN_ * H_ / 4;
    size_t stride = (size_t)gridDim.x * blockDim.x;
    for (size_t i = (size_t)blockIdx.x * blockDim.x + threadIdx.x; i < n; i += stride)
        dst[i] = src[i];
}

// ---------------- gates GEMM: [B,256] x [640,256]^T + biases ----------------
// BM=128, BN=128, BK=16, 256 threads, 8x8 register tile per thread.
__global__ __launch_bounds__(256) void gemm_gates_k(
    const float* __restrict__ x, const float* __restrict__ hx,
    const float* __restrict__ wih, const float* __restrict__ whh,
    const float* __restrict__ bih, const float* __restrict__ bhh)
{
    __shared__ __align__(16) float As[16][128];
    __shared__ __align__(16) float Ws[16][128];
    const int tid = threadIdx.x;
    const int rowBase = blockIdx.x * 128;
    const int colBase = blockIdx.y * 128;
    const int tx = tid & 15, ty = tid >> 4;
    const int lr = tid >> 2;        // 0..63
    const int lk = (tid & 3) * 4;   // 0,4,8,12

    float acc[8][8];
#pragma unroll
    for (int i = 0; i < 8; i++)
#pragma unroll
        for (int j = 0; j < 8; j++) acc[i][j] = 0.f;

    for (int k0 = 0; k0 < 256; k0 += 16) {
        const float* Ap = (k0 < 128) ? (x + k0) : (hx + (k0 - 128));
        const float* Wp = (k0 < 128) ? (wih + k0) : (whh + (k0 - 128));
#pragma unroll
        for (int rep = 0; rep < 2; rep++) {
            int r = lr + rep * 64;
            float4 av = *(const float4*)(Ap + (size_t)(rowBase + r) * 128 + lk);
            As[lk + 0][r] = av.x; As[lk + 1][r] = av.y;
            As[lk + 2][r] = av.z; As[lk + 3][r] = av.w;
            float4 wv = *(const float4*)(Wp + (size_t)(colBase + r) * 128 + lk);
            Ws[lk + 0][r] = wv.x; Ws[lk + 1][r] = wv.y;
            Ws[lk + 2][r] = wv.z; Ws[lk + 3][r] = wv.w;
        }
        __syncthreads();
#pragma unroll
        for (int kk = 0; kk < 16; kk++) {
            float4 a0 = *(const float4*)&As[kk][ty * 8];
            float4 a1 = *(const float4*)&As[kk][ty * 8 + 4];
            float4 b0 = *(const float4*)&Ws[kk][tx * 8];
            float4 b1 = *(const float4*)&Ws[kk][tx * 8 + 4];
            float ra[8] = {a0.x, a0.y, a0.z, a0.w, a1.x, a1.y, a1.z, a1.w};
            float rb[8] = {b0.x, b0.y, b0.z, b0.w, b1.x, b1.y, b1.z, b1.w};
#pragma unroll
            for (int i = 0; i < 8; i++)
#pragma unroll
                for (int j = 0; j < 8; j++)
                    acc[i][j] += ra[i] * rb[j];
        }
        __syncthreads();
    }
#pragma unroll
    for (int i = 0; i < 8; i++) {
        int row = rowBase + ty * 8 + i;
#pragma unroll
        for (int j = 0; j < 8; j += 4) {
            int col = colBase + tx * 8 + j;
            float4 v;
            v.x = acc[i][j + 0] + __ldg(&bih[col + 0]) + __ldg(&bhh[col + 0]);
            v.y = acc[i][j + 1] + __ldg(&bih[col + 1]) + __ldg(&bhh[col + 1]);
            v.z = acc[i][j + 2] + __ldg(&bih[col + 2]) + __ldg(&bhh[col + 2]);
            v.w = acc[i][j + 3] + __ldg(&bih[col + 3]) + __ldg(&bhh[col + 3]);
            *(float4*)&g_gates[(size_t)row * GATES_ + col] = v;
        }
    }
}

// ---------------- fused gate-activations + neighborhood attention -----------
// one block per batch row; 128 threads (one per H element)
__global__ __launch_bounds__(128) void fused_attn_k(
    const float* __restrict__ cx, const int* __restrict__ gi,
    const float* __restrict__ memory)
{
    __shared__ float cs[KNB_][H_];   // 12.8 KB neighborhood
    __shared__ float cys[H_];
    __shared__ float sc[KNB_];
    int b = blockIdx.x;
    int h = threadIdx.x;
    int gx = gi[2 * b] + SW_;
    int gy = gi[2 * b + 1] + SW_;

    const float* gb = g_gates + (size_t)b * GATES_;
    float ig = sigmoidf_(gb[h]);
    float fg = sigmoidf_(gb[H_ + h]);
    float cg = tanhf(gb[2 * H_ + h]);
    float cy = fg * cx[(size_t)b * H_ + h] + ig * cg;
    cys[h] = cy;

#pragma unroll
    for (int k = 0; k < KNB_; k++) {
        int xi = gx + k / 5 - SW_;
        int yi = gy + k % 5 - SW_;
        cs[k][h] = memory[((size_t)xi * NN_ + yi) * H_ + h];
    }
    __syncthreads();

    // scores: score[k] = <cy, cs[k]>, 4 warps split the 25 k's
    int lane = h & 31, warp = h >> 5;
    for (int k = warp; k < KNB_; k += 4) {
        float s = 0.f;
#pragma unroll
        for (int q = 0; q < 4; q++) s += cs[k][lane + 32 * q] * cys[lane + 32 * q];
#pragma unroll
        for (int off = 16; off > 0; off >>= 1) s += __shfl_xor_sync(0xffffffffu, s, off);
        if (lane == 0) sc[k] = s;
    }
    __syncthreads();

    // softmax over 25 (computed redundantly per thread; smem broadcast reads)
    float mx = -1e30f;
#pragma unroll
    for (int k = 0; k < KNB_; k++) mx = fmaxf(mx, sc[k]);
    float e[KNB_];
    float ssum = 0.f;
#pragma unroll
    for (int k = 0; k < KNB_; k++) { e[k] = __expf(sc[k] - mx); ssum += e[k]; }
    float inv = 1.0f / ssum;

    float mix = 0.f;
#pragma unroll
    for (int k = 0; k < KNB_; k++) mix += e[k] * cs[k][h];
    mix *= inv;

    g_combined[(size_t)b * (2 * H_) + h]      = mix;
    g_combined[(size_t)b * (2 * H_) + H_ + h] = cy;
}

// ---------------- attention output GEMM: tanh([B,256] x [128,256]^T + b) ----
__global__ __launch_bounds__(256) void gemm_attn_k(
    const float* __restrict__ attn_w, const float* __restrict__ attn_b)
{
    __shared__ __align__(16) float As[16][128];
    __shared__ __align__(16) float Ws[16][128];
    const int tid = threadIdx.x;
    const int rowBase = blockIdx.x * 128;
    const int tx = tid & 15, ty = tid >> 4;
    const int lr = tid >> 2;
    const int lk = (tid & 3) * 4;

    float acc[8][8];
#pragma unroll
    for (int i = 0; i < 8; i++)
#pragma unroll
        for (int j = 0; j < 8; j++) acc[i][j] = 0.f;

    for (int k0 = 0; k0 < 256; k0 += 16) {
#pragma unroll
        for (int rep = 0; rep < 2; rep++) {
            int r = lr + rep * 64;
            float4 av = *(const float4*)(g_combined + (size_t)(rowBase + r) * 256 + k0 + lk);
            As[lk + 0][r] = av.x; As[lk + 1][r] = av.y;
            As[lk + 2][r] = av.z; As[lk + 3][r] = av.w;
            float4 wv = *(const float4*)(attn_w + (size_t)r * 256 + k0 + lk);
            Ws[lk + 0][r] = wv.x; Ws[lk + 1][r] = wv.y;
            Ws[lk + 2][r] = wv.z; Ws[lk + 3][r] = wv.w;
        }
        __syncthreads();
#pragma unroll
        for (int kk = 0; kk < 16; kk++) {
            float4 a0 = *(const float4*)&As[kk][ty * 8];
            float4 a1 = *(const float4*)&As[kk][ty * 8 + 4];
            float4 b0 = *(const float4*)&Ws[kk][tx * 8];
            float4 b1 = *(const float4*)&Ws[kk][tx * 8 + 4];
            float ra[8] = {a0.x, a0.y, a0.z, a0.w, a1.x, a1.y, a1.z, a1.w};
            float rb[8] = {b0.x, b0.y, b0.z, b0.w, b1.x, b1.y, b1.z, b1.w};
#pragma unroll
            for (int i = 0; i < 8; i++)
#pragma unroll
                for (int j = 0; j < 8; j++)
                    acc[i][j] += ra[i] * rb[j];
        }
        __syncthreads();
    }
#pragma unroll
    for (int i = 0; i < 8; i++) {
        int row = rowBase + ty * 8 + i;
#pragma unroll
        for (int j = 0; j < 8; j += 4) {
            int col = tx * 8 + j;
            float4 v;
            v.x = tanhf(acc[i][j + 0] + __ldg(&attn_b[col + 0]));
            v.y = tanhf(acc[i][j + 1] + __ldg(&attn_b[col + 1]));
            v.z = tanhf(acc[i][j + 2] + __ldg(&attn_b[col + 2]));
            v.w = tanhf(acc[i][j + 3] + __ldg(&attn_b[col + 3]));
            *(float4*)&g_atten[(size_t)row * H_ + col] = v;
        }
    }
}

// ---------------- final elementwise: c, hy, scatter into mem_new ------------
__global__ __launch_bounds__(128) void final_k(
    const float* __restrict__ cx, const int* __restrict__ gi,
    const float* __restrict__ memory,
    float* __restrict__ out_hy, float* __restrict__ out_c,
    float* __restrict__ out_mem)
{
    int b = blockIdx.x;
    int h = threadIdx.x;
    const float* gb = g_gates + (size_t)b * GATES_;
    float ig = sigmoidf_(gb[h]);
    float fg = sigmoidf_(gb[H_ + h]);
    float cg = tanhf(gb[2 * H_ + h]);
    float og = sigmoidf_(gb[3 * H_ + h]);
    float sg = sigmoidf_(gb[4 * H_ + h]);
    float cy = fg * cx[(size_t)b * H_ + h] + ig * cg;
    float at = g_atten[(size_t)b * H_ + h];
    float c = cy + sg * at;
    float hy = og * tanhf(c);
    out_hy[(size_t)b * H_ + h] = hy;
    out_c[(size_t)b * H_ + h] = c;

    int gx = gi[2 * b] + SW_;
    int gy = gi[2 * b + 1] + SW_;
    int cell = gx * NN_ + gy;
    if (g_owner[cell] == b) {
        float m = memory[(size_t)cell * H_ + h];
        out_mem[(size_t)cell * H_ + h] = sg * m + (1.0f - sg) * c;
    }
}

// ---------------- launcher --------------------------------------------------
extern "C" void kernel_launch(void* const* d_in, const int* in_sizes, int n_in,
                              void* d_out, int out_size) {
    (void)in_sizes; (void)n_in; (void)out_size;
    const float* x      = (const float*)d_in[0];
    const int*   gi     = (const int*)d_in[1];
    const float* hx     = (const float*)d_in[2];
    const float* cx     = (const float*)d_in[3];
    const float* wih    = (const float*)d_in[4];
    const float* whh    = (const float*)d_in[5];
    const float* bih    = (const float*)d_in[6];
    const float* bhh    = (const float*)d_in[7];
    const float* attn_w = (const float*)d_in[8];
    const float* attn_b = (const float*)d_in[9];
    const float* memory = (const float*)d_in[10];

    float* out     = (float*)d_out;
    float* out_hy  = out;
    float* out_c   = out + (size_t)B_ * H_;
    float* out_mem = out + (size_t)2 * B_ * H_;

    reset_owner_k<<<(NN_ * NN_ + 511) / 512, 512>>>();
    owner_k<<<B_ / 256, 256>>>(gi);
    gemm_gates_k<<<dim3(B_ / 128, GATES_ / 128), 256>>>(x, hx, wih, whh, bih, bhh);
    fused_attn_k<<<B_, 128>>>(cx, gi, memory);
    gemm_attn_k<<<B_ / 128, 256>>>(attn_w, attn_b);
    copy_mem_k<<<16384, 256>>>((const float4*)memory, (float4*)out_mem);
    final_k<<<B_, 128>>>(cx, gi, memory, out_hy, out_c, out_mem);
}

// round 4
// speedup vs baseline: 1.0203x; 1.0203x over previous
#include <cuda_runtime.h>

// Problem constants
#define B_     16384
#define H_     128
#define G_     1100
#define SW_    2
#define NN_    1106      // G + 3*SW
#define GATES_ 640       // 5*H
#define KNB_   25        // (2*SW+1)^2

#define GEMM_BLOCKS_   640           // (16384/128) * (640/128)
#define COPYA_BLOCKS_  3456          // copy helpers inside gemm_copy_k
#define COPYB_BLOCKS_  4096          // copy helpers inside fused_attn_k
#define N4_            ((size_t)NN_ * NN_ * (H_ / 4))   // total float4s in memory
#define SPLIT4_        ((N4_ * 7) / 10)                 // 70% copied by kernel A

// ---------------- scratch (device globals; no allocation allowed) -----------
__device__ float g_gates[(size_t)B_ * GATES_];     // 40 MB  [B,640]
__device__ float g_combined[(size_t)B_ * 2 * H_];  // 16 MB  [B,256] = [mix | cy_h]
__device__ int   g_owner[NN_ * NN_];               // 4.9 MB last-writer map

__device__ __forceinline__ float sigmoidf_(float v) {
    return 1.0f / (1.0f + __expf(-v));
}

// strided range copy with 4 loads in flight
__device__ __forceinline__ void copy_range_(const float4* __restrict__ src,
                                            float4* __restrict__ dst,
                                            size_t i, size_t end, size_t stride)
{
    for (; i + 3 * stride < end; i += 4 * stride) {
        float4 v0 = src[i];
        float4 v1 = src[i + stride];
        float4 v2 = src[i + 2 * stride];
        float4 v3 = src[i + 3 * stride];
        dst[i] = v0;
        dst[i + stride] = v1;
        dst[i + 2 * stride] = v2;
        dst[i + 3 * stride] = v3;
    }
    for (; i < end; i += stride) dst[i] = src[i];
}

// ---------------- owner map (deterministic duplicate-scatter resolution) ----
__global__ void reset_owner_k() {
    int i = blockIdx.x * blockDim.x + threadIdx.x;
    if (i < NN_ * NN_) g_owner[i] = -1;
}

__global__ void owner_k(const int* __restrict__ gi) {
    int b = blockIdx.x * blockDim.x + threadIdx.x;
    int gx = gi[2 * b] + SW_;
    int gy = gi[2 * b + 1] + SW_;
    atomicMax(&g_owner[gx * NN_ + gy], b);
}

// ---------------- fused: gates GEMM + first 70% of the memory copy ----------
// Blocks [0, 640): 128x128x(BK=16) fp32 register-tiled GEMM for the 5-gate
// pre-activations. Blocks [640, 640+COPYA): stream-copy memory -> out_mem.
// The GEMM is FMA-bound with ~60MB DRAM traffic; the copy is pure DRAM --
// one launch overlaps the two pipes without streams/events.
__global__ __launch_bounds__(256) void gemm_copy_k(
    const float* __restrict__ x, const float* __restrict__ hx,
    const float* __restrict__ wih, const float* __restrict__ whh,
    const float* __restrict__ bih, const float* __restrict__ bhh,
    const float4* __restrict__ mem4, float4* __restrict__ out4)
{
    if (blockIdx.x >= GEMM_BLOCKS_) {
        const size_t stride = (size_t)COPYA_BLOCKS_ * 256;
        size_t i = (size_t)(blockIdx.x - GEMM_BLOCKS_) * 256 + threadIdx.x;
        copy_range_(mem4, out4, i, SPLIT4_, stride);
        return;
    }

    __shared__ __align__(16) float As[16][128];
    __shared__ __align__(16) float Ws[16][128];
    const int tid = threadIdx.x;
    const int rowBase = (blockIdx.x % 128) * 128;
    const int colBase = (blockIdx.x / 128) * 128;
    const int tx = tid & 15, ty = tid >> 4;
    const int lr = tid >> 2;        // 0..63
    const int lk = (tid & 3) * 4;   // 0,4,8,12

    float acc[8][8];
#pragma unroll
    for (int i = 0; i < 8; i++)
#pragma unroll
        for (int j = 0; j < 8; j++) acc[i][j] = 0.f;

    for (int k0 = 0; k0 < 256; k0 += 16) {
        const float* Ap = (k0 < 128) ? (x + k0) : (hx + (k0 - 128));
        const float* Wp = (k0 < 128) ? (wih + k0) : (whh + (k0 - 128));
#pragma unroll
        for (int rep = 0; rep < 2; rep++) {
            int r = lr + rep * 64;
            float4 av = *(const float4*)(Ap + (size_t)(rowBase + r) * 128 + lk);
            As[lk + 0][r] = av.x; As[lk + 1][r] = av.y;
            As[lk + 2][r] = av.z; As[lk + 3][r] = av.w;
            float4 wv = *(const float4*)(Wp + (size_t)(colBase + r) * 128 + lk);
            Ws[lk + 0][r] = wv.x; Ws[lk + 1][r] = wv.y;
            Ws[lk + 2][r] = wv.z; Ws[lk + 3][r] = wv.w;
        }
        __syncthreads();
#pragma unroll
        for (int kk = 0; kk < 16; kk++) {
            float4 a0 = *(const float4*)&As[kk][ty * 8];
            float4 a1 = *(const float4*)&As[kk][ty * 8 + 4];
            float4 b0 = *(const float4*)&Ws[kk][tx * 8];
            float4 b1 = *(const float4*)&Ws[kk][tx * 8 + 4];
            float ra[8] = {a0.x, a0.y, a0.z, a0.w, a1.x, a1.y, a1.z, a1.w};
            float rb[8] = {b0.x, b0.y, b0.z, b0.w, b1.x, b1.y, b1.z, b1.w};
#pragma unroll
            for (int i = 0; i < 8; i++)
#pragma unroll
                for (int j = 0; j < 8; j++)
                    acc[i][j] += ra[i] * rb[j];
        }
        __syncthreads();
    }
#pragma unroll
    for (int i = 0; i < 8; i++) {
        int row = rowBase + ty * 8 + i;
#pragma unroll
        for (int j = 0; j < 8; j += 4) {
            int col = colBase + tx * 8 + j;
            float4 v;
            v.x = acc[i][j + 0] + __ldg(&bih[col + 0]) + __ldg(&bhh[col + 0]);
            v.y = acc[i][j + 1] + __ldg(&bih[col + 1]) + __ldg(&bhh[col + 1]);
            v.z = acc[i][j + 2] + __ldg(&bih[col + 2]) + __ldg(&bhh[col + 2]);
            v.w = acc[i][j + 3] + __ldg(&bih[col + 3]) + __ldg(&bhh[col + 3]);
            *(float4*)&g_gates[(size_t)row * GATES_ + col] = v;
        }
    }
}

// ---------------- fused: gate-activations + attention + last 30% of copy ----
// Blocks [0, B): one block per batch row, 128 threads (one per H element).
// Blocks [B, B+COPYB): remaining memory copy (attn alone only used 48% DRAM).
__global__ __launch_bounds__(128) void fused_attn_k(
    const float* __restrict__ cx, const int* __restrict__ gi,
    const float* __restrict__ memory,
    const float4* __restrict__ mem4, float4* __restrict__ out4)
{
    if (blockIdx.x >= B_) {
        const size_t stride = (size_t)COPYB_BLOCKS_ * 128;
        size_t i = SPLIT4_ + (size_t)(blockIdx.x - B_) * 128 + threadIdx.x;
        copy_range_(mem4, out4, i, N4_, stride);
        return;
    }

    __shared__ float cs[KNB_][H_];   // 12.8 KB neighborhood
    __shared__ float cys[H_];
    __shared__ float sc[KNB_];
    int b = blockIdx.x;
    int h = threadIdx.x;
    int gx = gi[2 * b] + SW_;
    int gy = gi[2 * b + 1] + SW_;

    const float* gb = g_gates + (size_t)b * GATES_;
    float ig = sigmoidf_(gb[h]);
    float fg = sigmoidf_(gb[H_ + h]);
    float cg = tanhf(gb[2 * H_ + h]);
    float cy = fg * cx[(size_t)b * H_ + h] + ig * cg;
    cys[h] = cy;

#pragma unroll
    for (int k = 0; k < KNB_; k++) {
        int xi = gx + k / 5 - SW_;
        int yi = gy + k % 5 - SW_;
        cs[k][h] = memory[((size_t)xi * NN_ + yi) * H_ + h];
    }
    __syncthreads();

    // scores: score[k] = <cy, cs[k]>, 4 warps split the 25 k's
    int lane = h & 31, warp = h >> 5;
    for (int k = warp; k < KNB_; k += 4) {
        float s = 0.f;
#pragma unroll
        for (int q = 0; q < 4; q++) s += cs[k][lane + 32 * q] * cys[lane + 32 * q];
#pragma unroll
        for (int off = 16; off > 0; off >>= 1) s += __shfl_xor_sync(0xffffffffu, s, off);
        if (lane == 0) sc[k] = s;
    }
    __syncthreads();

    // softmax over 25 (computed redundantly per thread; smem broadcast reads)
    float mx = -1e30f;
#pragma unroll
    for (int k = 0; k < KNB_; k++) mx = fmaxf(mx, sc[k]);
    float e[KNB_];
    float ssum = 0.f;
#pragma unroll
    for (int k = 0; k < KNB_; k++) { e[k] = __expf(sc[k] - mx); ssum += e[k]; }
    float inv = 1.0f / ssum;

    float mix = 0.f;
#pragma unroll
    for (int k = 0; k < KNB_; k++) mix += e[k] * cs[k][h];
    mix *= inv;

    g_combined[(size_t)b * (2 * H_) + h]      = mix;
    g_combined[(size_t)b * (2 * H_) + H_ + h] = cy;
}

// ------- attention output GEMM + fused LSTM epilogue + memory scatter -------
// atten = tanh([B,256] x attn_w^T + attn_b); then directly:
//   c  = cy + sg*atten ; hy = og*tanh(c) ; owner-cell scatter into out_mem.
// The copy into out_mem finished in the two kernels above (same stream), so
// the scatter here is safely ordered.
__global__ __launch_bounds__(256) void gemm_attn_final_k(
    const float* __restrict__ attn_w, const float* __restrict__ attn_b,
    const int* __restrict__ gi, const float* __restrict__ memory,
    float* __restrict__ out_hy, float* __restrict__ out_c,
    float* __restrict__ out_mem)
{
    __shared__ __align__(16) float As[16][128];
    __shared__ __align__(16) float Ws[16][128];
    const int tid = threadIdx.x;
    const int rowBase = blockIdx.x * 128;
    const int tx = tid & 15, ty = tid >> 4;
    const int lr = tid >> 2;
    const int lk = (tid & 3) * 4;

    float acc[8][8];
#pragma unroll
    for (int i = 0; i < 8; i++)
#pragma unroll
        for (int j = 0; j < 8; j++) acc[i][j] = 0.f;

    for (int k0 = 0; k0 < 256; k0 += 16) {
#pragma unroll
        for (int rep = 0; rep < 2; rep++) {
            int r = lr + rep * 64;
            float4 av = *(const float4*)(g_combined + (size_t)(rowBase + r) * 256 + k0 + lk);
            As[lk + 0][r] = av.x; As[lk + 1][r] = av.y;
            As[lk + 2][r] = av.z; As[lk + 3][r] = av.w;
            float4 wv = *(const float4*)(attn_w + (size_t)r * 256 + k0 + lk);
            Ws[lk + 0][r] = wv.x; Ws[lk + 1][r] = wv.y;
            Ws[lk + 2][r] = wv.z; Ws[lk + 3][r] = wv.w;
        }
        __syncthreads();
#pragma unroll
        for (int kk = 0; kk < 16; kk++) {
            float4 a0 = *(const float4*)&As[kk][ty * 8];
            float4 a1 = *(const float4*)&As[kk][ty * 8 + 4];
            float4 b0 = *(const float4*)&Ws[kk][tx * 8];
            float4 b1 = *(const float4*)&Ws[kk][tx * 8 + 4];
            float ra[8] = {a0.x, a0.y, a0.z, a0.w, a1.x, a1.y, a1.z, a1.w};
            float rb[8] = {b0.x, b0.y, b0.z, b0.w, b1.x, b1.y, b1.z, b1.w};
#pragma unroll
            for (int i = 0; i < 8; i++)
#pragma unroll
                for (int j = 0; j < 8; j++)
                    acc[i][j] += ra[i] * rb[j];
        }
        __syncthreads();
    }

#pragma unroll
    for (int i = 0; i < 8; i++) {
        int row = rowBase + ty * 8 + i;
        const float* gb = g_gates + (size_t)row * GATES_;
        int gxr = gi[2 * row] + SW_;
        int gyr = gi[2 * row + 1] + SW_;
        int cell = gxr * NN_ + gyr;
        bool own = (g_owner[cell] == row);
#pragma unroll
        for (int j = 0; j < 8; j += 4) {
            int col = tx * 8 + j;
            float4 og4 = *(const float4*)(gb + 3 * H_ + col);
            float4 sg4 = *(const float4*)(gb + 4 * H_ + col);
            float4 cy4 = *(const float4*)(g_combined + (size_t)row * 256 + H_ + col);
            float at0 = tanhf(acc[i][j + 0] + __ldg(&attn_b[col + 0]));
            float at1 = tanhf(acc[i][j + 1] + __ldg(&attn_b[col + 1]));
            float at2 = tanhf(acc[i][j + 2] + __ldg(&attn_b[col + 2]));
            float at3 = tanhf(acc[i][j + 3] + __ldg(&attn_b[col + 3]));
            float s0 = sigmoidf_(sg4.x), s1 = sigmoidf_(sg4.y);
            float s2 = sigmoidf_(sg4.z), s3 = sigmoidf_(sg4.w);
            float4 c4;
            c4.x = cy4.x + s0 * at0;
            c4.y = cy4.y + s1 * at1;
            c4.z = cy4.z + s2 * at2;
            c4.w = cy4.w + s3 * at3;
            float4 hy4;
            hy4.x = sigmoidf_(og4.x) * tanhf(c4.x);
            hy4.y = sigmoidf_(og4.y) * tanhf(c4.y);
            hy4.z = sigmoidf_(og4.z) * tanhf(c4.z);
            hy4.w = sigmoidf_(og4.w) * tanhf(c4.w);
            *(float4*)&out_c[(size_t)row * H_ + col] = c4;
            *(float4*)&out_hy[(size_t)row * H_ + col] = hy4;
            if (own) {
                float4 m4 = *(const float4*)(memory + (size_t)cell * H_ + col);
                float4 u4;
                u4.x = s0 * m4.x + (1.0f - s0) * c4.x;
                u4.y = s1 * m4.y + (1.0f - s1) * c4.y;
                u4.z = s2 * m4.z + (1.0f - s2) * c4.z;
                u4.w = s3 * m4.w + (1.0f - s3) * c4.w;
                *(float4*)&out_mem[(size_t)cell * H_ + col] = u4;
            }
        }
    }
}

// ---------------- launcher --------------------------------------------------
extern "C" void kernel_launch(void* const* d_in, const int* in_sizes, int n_in,
                              void* d_out, int out_size) {
    (void)in_sizes; (void)n_in; (void)out_size;
    const float* x      = (const float*)d_in[0];
    const int*   gi     = (const int*)d_in[1];
    const float* hx     = (const float*)d_in[2];
    const float* cx     = (const float*)d_in[3];
    const float* wih    = (const float*)d_in[4];
    const float* whh    = (const float*)d_in[5];
    const float* bih    = (const float*)d_in[6];
    const float* bhh    = (const float*)d_in[7];
    const float* attn_w = (const float*)d_in[8];
    const float* attn_b = (const float*)d_in[9];
    const float* memory = (const float*)d_in[10];

    float* out     = (float*)d_out;
    float* out_hy  = out;
    float* out_c   = out + (size_t)B_ * H_;
    float* out_mem = out + (size_t)2 * B_ * H_;

    reset_owner_k<<<(NN_ * NN_ + 511) / 512, 512>>>();
    owner_k<<<B_ / 256, 256>>>(gi);
    // gates GEMM fused with 70% of the big memory copy (DRAM + FMA overlap)
    gemm_copy_k<<<GEMM_BLOCKS_ + COPYA_BLOCKS_, 256>>>(
        x, hx, wih, whh, bih, bhh, (const float4*)memory, (float4*)out_mem);
    // attention fused with the remaining 30% of the copy
    fused_attn_k<<<B_ + COPYB_BLOCKS_, 128>>>(
        cx, gi, memory, (const float4*)memory, (float4*)out_mem);
    // attention-output GEMM with fused LSTM epilogue + owner-cell scatter
    gemm_attn_final_k<<<B_ / 128, 256>>>(
        attn_w, attn_b, gi, memory, out_hy, out_c, out_mem);
}

// round 5
// speedup vs baseline: 1.0582x; 1.0371x over previous
#include <cuda_runtime.h>

// Problem constants
#define B_     16384
#define H_     128
#define G_     1100
#define SW_    2
#define NN_    1106      // G + 3*SW
#define GATES_ 640       // 5*H
#define KNB_   25        // (2*SW+1)^2

// Kernel A: 4096 blocks, every 32: 5 GEMM + 27 copy (interleaved in dispatch order)
#define A_TOTAL_BLOCKS_ 4096
#define GEMM_BLOCKS_    640
#define COPYA_BLOCKS_   3456
// Kernel B: 20480 blocks, every 5: 4 attn + 1 copy
#define B_TOTAL_BLOCKS_ 20480
#define COPYB_BLOCKS_   4096

#define N4_     ((size_t)NN_ * NN_ * (H_ / 4))   // total float4s in memory
#define SPLIT4_ ((N4_ * 7) / 10)                 // 70% copied by kernel A

// ---------------- scratch (device globals; no allocation allowed) -----------
__device__ float g_gates[(size_t)B_ * GATES_];     // 40 MB  [B,640]
__device__ float g_combined[(size_t)B_ * 2 * H_];  // 16 MB  [B,256] = [mix | cy_h]
__device__ int   g_owner[NN_ * NN_];               // 4.9 MB last-writer map

__device__ __forceinline__ float sigmoidf_(float v) {
    return 1.0f / (1.0f + __expf(-v));
}

// strided range copy with 4 loads in flight
__device__ __forceinline__ void copy_range_(const float4* __restrict__ src,
                                            float4* __restrict__ dst,
                                            size_t i, size_t end, size_t stride)
{
    for (; i + 3 * stride < end; i += 4 * stride) {
        float4 v0 = src[i];
        float4 v1 = src[i + stride];
        float4 v2 = src[i + 2 * stride];
        float4 v3 = src[i + 3 * stride];
        dst[i] = v0;
        dst[i + stride] = v1;
        dst[i + 2 * stride] = v2;
        dst[i + 3 * stride] = v3;
    }
    for (; i < end; i += stride) dst[i] = src[i];
}

// ---------------- owner map (deterministic duplicate-scatter resolution) ----
__global__ void reset_owner_k() {
    int i = blockIdx.x * blockDim.x + threadIdx.x;
    if (i < NN_ * NN_) g_owner[i] = -1;
}

__global__ void owner_k(const int* __restrict__ gi) {
    int b = blockIdx.x * blockDim.x + threadIdx.x;
    int gx = gi[2 * b] + SW_;
    int gy = gi[2 * b + 1] + SW_;
    atomicMax(&g_owner[gx * NN_ + gy], b);
}

// ---------------- fused: gates GEMM + first 70% of the memory copy ----------
// Roles interleaved by block index (5 GEMM + 27 copy per 32-block group) so
// every scheduling wave carries both FMA-bound and DRAM-bound blocks --
// the previous append-ordering serialized them inside the launch.
__global__ __launch_bounds__(256) void gemm_copy_k(
    const float* __restrict__ x, const float* __restrict__ hx,
    const float* __restrict__ wih, const float* __restrict__ whh,
    const float* __restrict__ bih, const float* __restrict__ bhh,
    const float4* __restrict__ mem4, float4* __restrict__ out4)
{
    const int bid = blockIdx.x;
    const int grp = bid >> 5;
    const int lane32 = bid & 31;

    if (lane32 >= 5) {
        // ---- copy role ----
        const int cid = grp * 27 + (lane32 - 5);
        const size_t stride = (size_t)COPYA_BLOCKS_ * 256;
        size_t i = (size_t)cid * 256 + threadIdx.x;
        copy_range_(mem4, out4, i, SPLIT4_, stride);
        return;
    }

    // ---- GEMM role ----
    const int gemm_id = grp * 5 + lane32;   // 0..639
    __shared__ __align__(16) float As[16][128];
    __shared__ __align__(16) float Ws[16][128];
    const int tid = threadIdx.x;
    const int rowBase = (gemm_id % 128) * 128;
    const int colBase = (gemm_id / 128) * 128;
    const int tx = tid & 15, ty = tid >> 4;
    const int lr = tid >> 2;        // 0..63
    const int lk = (tid & 3) * 4;   // 0,4,8,12

    float acc[8][8];
#pragma unroll
    for (int i = 0; i < 8; i++)
#pragma unroll
        for (int j = 0; j < 8; j++) acc[i][j] = 0.f;

    for (int k0 = 0; k0 < 256; k0 += 16) {
        const float* Ap = (k0 < 128) ? (x + k0) : (hx + (k0 - 128));
        const float* Wp = (k0 < 128) ? (wih + k0) : (whh + (k0 - 128));
#pragma unroll
        for (int rep = 0; rep < 2; rep++) {
            int r = lr + rep * 64;
            float4 av = *(const float4*)(Ap + (size_t)(rowBase + r) * 128 + lk);
            As[lk + 0][r] = av.x; As[lk + 1][r] = av.y;
            As[lk + 2][r] = av.z; As[lk + 3][r] = av.w;
            float4 wv = *(const float4*)(Wp + (size_t)(colBase + r) * 128 + lk);
            Ws[lk + 0][r] = wv.x; Ws[lk + 1][r] = wv.y;
            Ws[lk + 2][r] = wv.z; Ws[lk + 3][r] = wv.w;
        }
        __syncthreads();
#pragma unroll
        for (int kk = 0; kk < 16; kk++) {
            float4 a0 = *(const float4*)&As[kk][ty * 8];
            float4 a1 = *(const float4*)&As[kk][ty * 8 + 4];
            float4 b0 = *(const float4*)&Ws[kk][tx * 8];
            float4 b1 = *(const float4*)&Ws[kk][tx * 8 + 4];
            float ra[8] = {a0.x, a0.y, a0.z, a0.w, a1.x, a1.y, a1.z, a1.w};
            float rb[8] = {b0.x, b0.y, b0.z, b0.w, b1.x, b1.y, b1.z, b1.w};
#pragma unroll
            for (int i = 0; i < 8; i++)
#pragma unroll
                for (int j = 0; j < 8; j++)
                    acc[i][j] += ra[i] * rb[j];
        }
        __syncthreads();
    }
#pragma unroll
    for (int i = 0; i < 8; i++) {
        int row = rowBase + ty * 8 + i;
#pragma unroll
        for (int j = 0; j < 8; j += 4) {
            int col = colBase + tx * 8 + j;
            float4 v;
            v.x = acc[i][j + 0] + __ldg(&bih[col + 0]) + __ldg(&bhh[col + 0]);
            v.y = acc[i][j + 1] + __ldg(&bih[col + 1]) + __ldg(&bhh[col + 1]);
            v.z = acc[i][j + 2] + __ldg(&bih[col + 2]) + __ldg(&bhh[col + 2]);
            v.w = acc[i][j + 3] + __ldg(&bih[col + 3]) + __ldg(&bhh[col + 3]);
            *(float4*)&g_gates[(size_t)row * GATES_ + col] = v;
        }
    }
}

// ---------------- fused: gate-activations + attention + last 30% of copy ----
// Roles interleaved: every group of 5 blocks = 4 attn + 1 copy.
__global__ __launch_bounds__(128) void fused_attn_k(
    const float* __restrict__ cx, const int* __restrict__ gi,
    const float* __restrict__ memory,
    const float4* __restrict__ mem4, float4* __restrict__ out4)
{
    const int bid = blockIdx.x;
    if ((bid % 5) == 4) {
        // ---- copy role ----
        const int cid = bid / 5;   // 0..4095
        const size_t stride = (size_t)COPYB_BLOCKS_ * 128;
        size_t i = SPLIT4_ + (size_t)cid * 128 + threadIdx.x;
        copy_range_(mem4, out4, i, N4_, stride);
        return;
    }

    const int b = (bid / 5) * 4 + (bid % 5);   // 0..16383

    __shared__ float cs[KNB_][H_];   // 12.8 KB neighborhood
    __shared__ float cys[H_];
    __shared__ float sc[KNB_];
    int h = threadIdx.x;
    int gx = gi[2 * b] + SW_;
    int gy = gi[2 * b + 1] + SW_;

    const float* gb = g_gates + (size_t)b * GATES_;
    float ig = sigmoidf_(gb[h]);
    float fg = sigmoidf_(gb[H_ + h]);
    float cg = tanhf(gb[2 * H_ + h]);
    float cy = fg * cx[(size_t)b * H_ + h] + ig * cg;
    cys[h] = cy;

#pragma unroll
    for (int k = 0; k < KNB_; k++) {
        int xi = gx + k / 5 - SW_;
        int yi = gy + k % 5 - SW_;
        cs[k][h] = memory[((size_t)xi * NN_ + yi) * H_ + h];
    }
    __syncthreads();

    // scores: score[k] = <cy, cs[k]>, 4 warps split the 25 k's
    int lane = h & 31, warp = h >> 5;
    for (int k = warp; k < KNB_; k += 4) {
        float s = 0.f;
#pragma unroll
        for (int q = 0; q < 4; q++) s += cs[k][lane + 32 * q] * cys[lane + 32 * q];
#pragma unroll
        for (int off = 16; off > 0; off >>= 1) s += __shfl_xor_sync(0xffffffffu, s, off);
        if (lane == 0) sc[k] = s;
    }
    __syncthreads();

    // softmax over 25 (computed redundantly per thread; smem broadcast reads)
    float mx = -1e30f;
#pragma unroll
    for (int k = 0; k < KNB_; k++) mx = fmaxf(mx, sc[k]);
    float e[KNB_];
    float ssum = 0.f;
#pragma unroll
    for (int k = 0; k < KNB_; k++) { e[k] = __expf(sc[k] - mx); ssum += e[k]; }
    float inv = 1.0f / ssum;

    float mix = 0.f;
#pragma unroll
    for (int k = 0; k < KNB_; k++) mix += e[k] * cs[k][h];
    mix *= inv;

    g_combined[(size_t)b * (2 * H_) + h]      = mix;
    g_combined[(size_t)b * (2 * H_) + H_ + h] = cy;
}

// ------- attention output GEMM + fused LSTM epilogue + memory scatter -------
__global__ __launch_bounds__(256) void gemm_attn_final_k(
    const float* __restrict__ attn_w, const float* __restrict__ attn_b,
    const int* __restrict__ gi, const float* __restrict__ memory,
    float* __restrict__ out_hy, float* __restrict__ out_c,
    float* __restrict__ out_mem)
{
    __shared__ __align__(16) float As[16][128];
    __shared__ __align__(16) float Ws[16][128];
    const int tid = threadIdx.x;
    const int rowBase = blockIdx.x * 128;
    const int tx = tid & 15, ty = tid >> 4;
    const int lr = tid >> 2;
    const int lk = (tid & 3) * 4;

    float acc[8][8];
#pragma unroll
    for (int i = 0; i < 8; i++)
#pragma unroll
        for (int j = 0; j < 8; j++) acc[i][j] = 0.f;

    for (int k0 = 0; k0 < 256; k0 += 16) {
#pragma unroll
        for (int rep = 0; rep < 2; rep++) {
            int r = lr + rep * 64;
            float4 av = *(const float4*)(g_combined + (size_t)(rowBase + r) * 256 + k0 + lk);
            As[lk + 0][r] = av.x; As[lk + 1][r] = av.y;
            As[lk + 2][r] = av.z; As[lk + 3][r] = av.w;
            float4 wv = *(const float4*)(attn_w + (size_t)r * 256 + k0 + lk);
            Ws[lk + 0][r] = wv.x; Ws[lk + 1][r] = wv.y;
            Ws[lk + 2][r] = wv.z; Ws[lk + 3][r] = wv.w;
        }
        __syncthreads();
#pragma unroll
        for (int kk = 0; kk < 16; kk++) {
            float4 a0 = *(const float4*)&As[kk][ty * 8];
            float4 a1 = *(const float4*)&As[kk][ty * 8 + 4];
            float4 b0 = *(const float4*)&Ws[kk][tx * 8];
            float4 b1 = *(const float4*)&Ws[kk][tx * 8 + 4];
            float ra[8] = {a0.x, a0.y, a0.z, a0.w, a1.x, a1.y, a1.z, a1.w};
            float rb[8] = {b0.x, b0.y, b0.z, b0.w, b1.x, b1.y, b1.z, b1.w};
#pragma unroll
            for (int i = 0; i < 8; i++)
#pragma unroll
                for (int j = 0; j < 8; j++)
                    acc[i][j] += ra[i] * rb[j];
        }
        __syncthreads();
    }

#pragma unroll
    for (int i = 0; i < 8; i++) {
        int row = rowBase + ty * 8 + i;
        const float* gb = g_gates + (size_t)row * GATES_;
        int gxr = gi[2 * row] + SW_;
        int gyr = gi[2 * row + 1] + SW_;
        int cell = gxr * NN_ + gyr;
        bool own = (g_owner[cell] == row);
#pragma unroll
        for (int j = 0; j < 8; j += 4) {
            int col = tx * 8 + j;
            float4 og4 = *(const float4*)(gb + 3 * H_ + col);
            float4 sg4 = *(const float4*)(gb + 4 * H_ + col);
            float4 cy4 = *(const float4*)(g_combined + (size_t)row * 256 + H_ + col);
            float at0 = tanhf(acc[i][j + 0] + __ldg(&attn_b[col + 0]));
            float at1 = tanhf(acc[i][j + 1] + __ldg(&attn_b[col + 1]));
            float at2 = tanhf(acc[i][j + 2] + __ldg(&attn_b[col + 2]));
            float at3 = tanhf(acc[i][j + 3] + __ldg(&attn_b[col + 3]));
            float s0 = sigmoidf_(sg4.x), s1 = sigmoidf_(sg4.y);
            float s2 = sigmoidf_(sg4.z), s3 = sigmoidf_(sg4.w);
            float4 c4;
            c4.x = cy4.x + s0 * at0;
            c4.y = cy4.y + s1 * at1;
            c4.z = cy4.z + s2 * at2;
            c4.w = cy4.w + s3 * at3;
            float4 hy4;
            hy4.x = sigmoidf_(og4.x) * tanhf(c4.x);
            hy4.y = sigmoidf_(og4.y) * tanhf(c4.y);
            hy4.z = sigmoidf_(og4.z) * tanhf(c4.z);
            hy4.w = sigmoidf_(og4.w) * tanhf(c4.w);
            *(float4*)&out_c[(size_t)row * H_ + col] = c4;
            *(float4*)&out_hy[(size_t)row * H_ + col] = hy4;
            if (own) {
                float4 m4 = *(const float4*)(memory + (size_t)cell * H_ + col);
                float4 u4;
                u4.x = s0 * m4.x + (1.0f - s0) * c4.x;
                u4.y = s1 * m4.y + (1.0f - s1) * c4.y;
                u4.z = s2 * m4.z + (1.0f - s2) * c4.z;
                u4.w = s3 * m4.w + (1.0f - s3) * c4.w;
                *(float4*)&out_mem[(size_t)cell * H_ + col] = u4;
            }
        }
    }
}

// ---------------- launcher --------------------------------------------------
extern "C" void kernel_launch(void* const* d_in, const int* in_sizes, int n_in,
                              void* d_out, int out_size) {
    (void)in_sizes; (void)n_in; (void)out_size;
    const float* x      = (const float*)d_in[0];
    const int*   gi     = (const int*)d_in[1];
    const float* hx     = (const float*)d_in[2];
    const float* cx     = (const float*)d_in[3];
    const float* wih    = (const float*)d_in[4];
    const float* whh    = (const float*)d_in[5];
    const float* bih    = (const float*)d_in[6];
    const float* bhh    = (const float*)d_in[7];
    const float* attn_w = (const float*)d_in[8];
    const float* attn_b = (const float*)d_in[9];
    const float* memory = (const float*)d_in[10];

    float* out     = (float*)d_out;
    float* out_hy  = out;
    float* out_c   = out + (size_t)B_ * H_;
    float* out_mem = out + (size_t)2 * B_ * H_;

    reset_owner_k<<<(NN_ * NN_ + 511) / 512, 512>>>();
    owner_k<<<B_ / 256, 256>>>(gi);
    // gates GEMM + 70% of the big memory copy, roles interleaved per wave
    gemm_copy_k<<<A_TOTAL_BLOCKS_, 256>>>(
        x, hx, wih, whh, bih, bhh, (const float4*)memory, (float4*)out_mem);
    // attention + remaining 30% of the copy, roles interleaved per wave
    fused_attn_k<<<B_TOTAL_BLOCKS_, 128>>>(
        cx, gi, memory, (const float4*)memory, (float4*)out_mem);
    // attention-output GEMM with fused LSTM epilogue + owner-cell scatter
    gemm_attn_final_k<<<B_ / 128, 256>>>(
        attn_w, attn_b, gi, memory, out_hy, out_c, out_mem);
}

// round 15
// speedup vs baseline: 1.0900x; 1.0301x over previous
#include <cuda_runtime.h>

// Problem constants
#define B_     16384
#define H_     128
#define G_     1100
#define SW_    2
#define NN_    1106      // G + 3*SW
#define GATES_ 640      // 5*H
#define KNB_   25       // (2*SW+1)^2

#define GEMM_BLOCKS_    640      // (16384/128) * (640/128) tiles
#define WS_THREADS_     384      // 256 GEMM + 128 copy per block
#define COPYA_THREADS_  ((size_t)GEMM_BLOCKS_ * 128)
// Kernel B: 20480 blocks, every 5: 4 attn + 1 copy
#define B_TOTAL_BLOCKS_ 20480
#define COPYB_BLOCKS_   4096

#define N4_     ((size_t)NN_ * NN_ * (H_ / 4))   // total float4s in memory
#define SPLIT4_ ((N4_ * 7) / 10)                 // 70% copied by kernel A

// ---------------- scratch (device globals; no allocation allowed) -----------
__device__ float g_gates[(size_t)B_ * GATES_];     // 40 MB  [B,640]
__device__ float g_combined[(size_t)B_ * 2 * H_];  // 16 MB  [B,256] = [mix | cy_h]
__device__ int   g_owner[NN_ * NN_];               // 4.9 MB last-writer map

__device__ __forceinline__ float sigmoidf_(float v) {
    return 1.0f / (1.0f + __expf(-v));
}

// named barrier for the GEMM sub-group (threads 0..255); copy warps never join
__device__ __forceinline__ void gemm_bar_() {
    asm volatile("bar.sync 1, 256;" ::: "memory");
}

// strided range copy, 8 float4 in flight; streaming hints (__ldcs/__stwt) so
// the 1.25GB stream doesn't evict GEMM operands / gather lines from L2.
__device__ __forceinline__ void copy_range_(const float4* __restrict__ src,
                                            float4* __restrict__ dst,
                                            size_t i, size_t end, size_t stride)
{
    for (; i + 7 * stride < end; i += 8 * stride) {
        float4 v0 = __ldcs(&src[i]);
        float4 v1 = __ldcs(&src[i + stride]);
        float4 v2 = __ldcs(&src[i + 2 * stride]);
        float4 v3 = __ldcs(&src[i + 3 * stride]);
        float4 v4 = __ldcs(&src[i + 4 * stride]);
        float4 v5 = __ldcs(&src[i + 5 * stride]);
        float4 v6 = __ldcs(&src[i + 6 * stride]);
        float4 v7 = __ldcs(&src[i + 7 * stride]);
        __stwt(&dst[i], v0);
        __stwt(&dst[i + stride], v1);
        __stwt(&dst[i + 2 * stride], v2);
        __stwt(&dst[i + 3 * stride], v3);
        __stwt(&dst[i + 4 * stride], v4);
        __stwt(&dst[i + 5 * stride], v5);
        __stwt(&dst[i + 6 * stride], v6);
        __stwt(&dst[i + 7 * stride], v7);
    }
    for (; i < end; i += stride) __stwt(&dst[i], __ldcs(&src[i]));
}

// ---------------- owner map (deterministic duplicate-scatter resolution) ----
__global__ void reset_owner_k() {
    int i = blockIdx.x * blockDim.x + threadIdx.x;
    if (i < NN_ * NN_) g_owner[i] = -1;
}

__global__ void owner_k(const int* __restrict__ gi) {
    int b = blockIdx.x * blockDim.x + threadIdx.x;
    int gx = gi[2 * b] + SW_;
    int gy = gi[2 * b + 1] + SW_;
    atomicMax(&g_owner[gx * NN_ + gy], b);
}

// ------ warp-specialized: gates GEMM (256 thr) + memory copy (128 thr) ------
// Co-residency of the FMA-bound GEMM and the DRAM-bound copy is guaranteed by
// construction: they share one block. The GEMM sub-group syncs with a named
// barrier so the copy warps free-run through their streaming loop. 640 blocks,
// ~1/SM (register-limited), ~4.3 waves; every resident SM always drives both
// the FMA pipe and its DRAM share.
__global__ __launch_bounds__(WS_THREADS_) void gemm_copy_ws_k(
    const float* __restrict__ x, const float* __restrict__ hx,
    const float* __restrict__ wih, const float* __restrict__ whh,
    const float* __restrict__ bih, const float* __restrict__ bhh,
    const float4* __restrict__ mem4, float4* __restrict__ out4)
{
    const int tid = threadIdx.x;

    if (tid >= 256) {
        // ---- copy role: threads 256..383, slice id = blockIdx.x ----
        const size_t stride = COPYA_THREADS_;
        size_t i = (size_t)blockIdx.x * 128 + (tid - 256);
        copy_range_(mem4, out4, i, SPLIT4_, stride);
        return;
    }

    // ---- GEMM role: 128x128x(BK=16), 8x8 register tile per thread ----
    __shared__ __align__(16) float As[16][128];
    __shared__ __align__(16) float Ws[16][128];
    const int seq = blockIdx.x;
    const int rowBase = (seq % 128) * 128;
    const int colBase = (seq / 128) * 128;
    const int tx = tid & 15, ty = tid >> 4;
    const int lr = tid >> 2;        // 0..63
    const int lk = (tid & 3) * 4;   // 0,4,8,12

    float acc[8][8];
#pragma unroll
    for (int i = 0; i < 8; i++)
#pragma unroll
        for (int j = 0; j < 8; j++) acc[i][j] = 0.f;

    for (int k0 = 0; k0 < 256; k0 += 16) {
        const float* Ap = (k0 < 128) ? (x + k0) : (hx + (k0 - 128));
        const float* Wp = (k0 < 128) ? (wih + k0) : (whh + (k0 - 128));
#pragma unroll
        for (int rep = 0; rep < 2; rep++) {
            int r = lr + rep * 64;
            float4 av = *(const float4*)(Ap + (size_t)(rowBase + r) * 128 + lk);
            As[lk + 0][r] = av.x; As[lk + 1][r] = av.y;
            As[lk + 2][r] = av.z; As[lk + 3][r] = av.w;
            float4 wv = *(const float4*)(Wp + (size_t)(colBase + r) * 128 + lk);
            Ws[lk + 0][r] = wv.x; Ws[lk + 1][r] = wv.y;
            Ws[lk + 2][r] = wv.z; Ws[lk + 3][r] = wv.w;
        }
        gemm_bar_();
#pragma unroll
        for (int kk = 0; kk < 16; kk++) {
            float4 a0 = *(const float4*)&As[kk][ty * 8];
            float4 a1 = *(const float4*)&As[kk][ty * 8 + 4];
            float4 b0 = *(const float4*)&Ws[kk][tx * 8];
            float4 b1 = *(const float4*)&Ws[kk][tx * 8 + 4];
            float ra[8] = {a0.x, a0.y, a0.z, a0.w, a1.x, a1.y, a1.z, a1.w};
            float rb[8] = {b0.x, b0.y, b0.z, b0.w, b1.x, b1.y, b1.z, b1.w};
#pragma unroll
            for (int i = 0; i < 8; i++)
#pragma unroll
                for (int j = 0; j < 8; j++)
                    acc[i][j] += ra[i] * rb[j];
        }
        gemm_bar_();
    }
#pragma unroll
    for (int i = 0; i < 8; i++) {
        int row = rowBase + ty * 8 + i;
#pragma unroll
        for (int j = 0; j < 8; j += 4) {
            int col = colBase + tx * 8 + j;
            float4 v;
            v.x = acc[i][j + 0] + __ldg(&bih[col + 0]) + __ldg(&bhh[col + 0]);
            v.y = acc[i][j + 1] + __ldg(&bih[col + 1]) + __ldg(&bhh[col + 1]);
            v.z = acc[i][j + 2] + __ldg(&bih[col + 2]) + __ldg(&bhh[col + 2]);
            v.w = acc[i][j + 3] + __ldg(&bih[col + 3]) + __ldg(&bhh[col + 3]);
            *(float4*)&g_gates[(size_t)row * GATES_ + col] = v;
        }
    }
}

// ---------------- fused: gate-activations + attention + last 30% of copy ----
// Roles interleaved: every group of 5 blocks = 4 attn + 1 copy (measured at
// 73.5% DRAM in R5 -- kept as-is).
__global__ __launch_bounds__(128) void fused_attn_k(
    const float* __restrict__ cx, const int* __restrict__ gi,
    const float* __restrict__ memory,
    const float4* __restrict__ mem4, float4* __restrict__ out4)
{
    const int bid = blockIdx.x;
    if ((bid % 5) == 4) {
        // ---- copy role ----
        const int cid = bid / 5;   // 0..4095
        const size_t stride = (size_t)COPYB_BLOCKS_ * 128;
        size_t i = SPLIT4_ + (size_t)cid * 128 + threadIdx.x;
        copy_range_(mem4, out4, i, N4_, stride);
        return;
    }

    const int b = (bid / 5) * 4 + (bid % 5);   // 0..16383

    __shared__ float cs[KNB_][H_];   // 12.8 KB neighborhood
    __shared__ float cys[H_];
    __shared__ float sc[KNB_];
    int h = threadIdx.x;
    int gx = gi[2 * b] + SW_;
    int gy = gi[2 * b + 1] + SW_;

    const float* gb = g_gates + (size_t)b * GATES_;
    float ig = sigmoidf_(gb[h]);
    float fg = sigmoidf_(gb[H_ + h]);
    float cg = tanhf(gb[2 * H_ + h]);
    float cy = fg * cx[(size_t)b * H_ + h] + ig * cg;
    cys[h] = cy;

#pragma unroll
    for (int k = 0; k < KNB_; k++) {
        int xi = gx + k / 5 - SW_;
        int yi = gy + k % 5 - SW_;
        cs[k][h] = memory[((size_t)xi * NN_ + yi) * H_ + h];
    }
    __syncthreads();

    // scores: score[k] = <cy, cs[k]>, 4 warps split the 25 k's
    int lane = h & 31, warp = h >> 5;
    for (int k = warp; k < KNB_; k += 4) {
        float s = 0.f;
#pragma unroll
        for (int q = 0; q < 4; q++) s += cs[k][lane + 32 * q] * cys[lane + 32 * q];
#pragma unroll
        for (int off = 16; off > 0; off >>= 1) s += __shfl_xor_sync(0xffffffffu, s, off);
        if (lane == 0) sc[k] = s;
    }
    __syncthreads();

    // softmax over 25 (computed redundantly per thread; smem broadcast reads)
    float mx = -1e30f;
#pragma unroll
    for (int k = 0; k < KNB_; k++) mx = fmaxf(mx, sc[k]);
    float e[KNB_];
    float ssum = 0.f;
#pragma unroll
    for (int k = 0; k < KNB_; k++) { e[k] = __expf(sc[k] - mx); ssum += e[k]; }
    float inv = 1.0f / ssum;

    float mix = 0.f;
#pragma unroll
    for (int k = 0; k < KNB_; k++) mix += e[k] * cs[k][h];
    mix *= inv;

    g_combined[(size_t)b * (2 * H_) + h]      = mix;
    g_combined[(size_t)b * (2 * H_) + H_ + h] = cy;
}

// ------- attention output GEMM + fused LSTM epilogue + memory scatter -------
__global__ __launch_bounds__(256) void gemm_attn_final_k(
    const float* __restrict__ attn_w, const float* __restrict__ attn_b,
    const int* __restrict__ gi, const float* __restrict__ memory,
    float* __restrict__ out_hy, float* __restrict__ out_c,
    float* __restrict__ out_mem)
{
    __shared__ __align__(16) float As[16][128];
    __shared__ __align__(16) float Ws[16][128];
    const int tid = threadIdx.x;
    const int rowBase = blockIdx.x * 128;
    const int tx = tid & 15, ty = tid >> 4;
    const int lr = tid >> 2;
    const int lk = (tid & 3) * 4;

    float acc[8][8];
#pragma unroll
    for (int i = 0; i < 8; i++)
#pragma unroll
        for (int j = 0; j < 8; j++) acc[i][j] = 0.f;

    for (int k0 = 0; k0 < 256; k0 += 16) {
#pragma unroll
        for (int rep = 0; rep < 2; rep++) {
            int r = lr + rep * 64;
            float4 av = *(const float4*)(g_combined + (size_t)(rowBase + r) * 256 + k0 + lk);
            As[lk + 0][r] = av.x; As[lk + 1][r] = av.y;
            As[lk + 2][r] = av.z; As[lk + 3][r] = av.w;
            float4 wv = *(const float4*)(attn_w + (size_t)r * 256 + k0 + lk);
            Ws[lk + 0][r] = wv.x; Ws[lk + 1][r] = wv.y;
            Ws[lk + 2][r] = wv.z; Ws[lk + 3][r] = wv.w;
        }
        __syncthreads();
#pragma unroll
        for (int kk = 0; kk < 16; kk++) {
            float4 a0 = *(const float4*)&As[kk][ty * 8];
            float4 a1 = *(const float4*)&As[kk][ty * 8 + 4];
            float4 b0 = *(const float4*)&Ws[kk][tx * 8];
            float4 b1 = *(const float4*)&Ws[kk][tx * 8 + 4];
            float ra[8] = {a0.x, a0.y, a0.z, a0.w, a1.x, a1.y, a1.z, a1.w};
            float rb[8] = {b0.x, b0.y, b0.z, b0.w, b1.x, b1.y, b1.z, b1.w};
#pragma unroll
            for (int i = 0; i < 8; i++)
#pragma unroll
                for (int j = 0; j < 8; j++)
                    acc[i][j] += ra[i] * rb[j];
        }
        __syncthreads();
    }

#pragma unroll
    for (int i = 0; i < 8; i++) {
        int row = rowBase + ty * 8 + i;
        const float* gb = g_gates + (size_t)row * GATES_;
        int gxr = gi[2 * row] + SW_;
        int gyr = gi[2 * row + 1] + SW_;
        int cell = gxr * NN_ + gyr;
        bool own = (g_owner[cell] == row);
#pragma unroll
        for (int j = 0; j < 8; j += 4) {
            int col = tx * 8 + j;
            float4 og4 = *(const float4*)(gb + 3 * H_ + col);
            float4 sg4 = *(const float4*)(gb + 4 * H_ + col);
            float4 cy4 = *(const float4*)(g_combined + (size_t)row * 256 + H_ + col);
            float at0 = tanhf(acc[i][j + 0] + __ldg(&attn_b[col + 0]));
            float at1 = tanhf(acc[i][j + 1] + __ldg(&attn_b[col + 1]));
            float at2 = tanhf(acc[i][j + 2] + __ldg(&attn_b[col + 2]));
            float at3 = tanhf(acc[i][j + 3] + __ldg(&attn_b[col + 3]));
            float s0 = sigmoidf_(sg4.x), s1 = sigmoidf_(sg4.y);
            float s2 = sigmoidf_(sg4.z), s3 = sigmoidf_(sg4.w);
            float4 c4;
            c4.x = cy4.x + s0 * at0;
            c4.y = cy4.y + s1 * at1;
            c4.z = cy4.z + s2 * at2;
            c4.w = cy4.w + s3 * at3;
            float4 hy4;
            hy4.x = sigmoidf_(og4.x) * tanhf(c4.x);
            hy4.y = sigmoidf_(og4.y) * tanhf(c4.y);
            hy4.z = sigmoidf_(og4.z) * tanhf(c4.z);
            hy4.w = sigmoidf_(og4.w) * tanhf(c4.w);
            *(float4*)&out_c[(size_t)row * H_ + col] = c4;
            *(float4*)&out_hy[(size_t)row * H_ + col] = hy4;
            if (own) {
                float4 m4 = *(const float4*)(memory + (size_t)cell * H_ + col);
                float4 u4;
                u4.x = s0 * m4.x + (1.0f - s0) * c4.x;
                u4.y = s1 * m4.y + (1.0f - s1) * c4.y;
                u4.z = s2 * m4.z + (1.0f - s2) * c4.z;
                u4.w = s3 * m4.w + (1.0f - s3) * c4.w;
                *(float4*)&out_mem[(size_t)cell * H_ + col] = u4;
            }
        }
    }
}

// ---------------- launcher --------------------------------------------------
extern "C" void kernel_launch(void* const* d_in, const int* in_sizes, int n_in,
                              void* d_out, int out_size) {
    (void)in_sizes; (void)n_in; (void)out_size;
    const float* x      = (const float*)d_in[0];
    const int*   gi     = (const int*)d_in[1];
    const float* hx     = (const float*)d_in[2];
    const float* cx     = (const float*)d_in[3];
    const float* wih    = (const float*)d_in[4];
    const float* whh    = (const float*)d_in[5];
    const float* bih    = (const float*)d_in[6];
    const float* bhh    = (const float*)d_in[7];
    const float* attn_w = (const float*)d_in[8];
    const float* attn_b = (const float*)d_in[9];
    const float* memory = (const float*)d_in[10];

    float* out     = (float*)d_out;
    float* out_hy  = out;
    float* out_c   = out + (size_t)B_ * H_;
    float* out_mem = out + (size_t)2 * B_ * H_;

    reset_owner_k<<<(NN_ * NN_ + 511) / 512, 512>>>();
    owner_k<<<B_ / 256, 256>>>(gi);
    // gates GEMM + 70% of the big memory copy, warp-specialized in one block
    gemm_copy_ws_k<<<GEMM_BLOCKS_, WS_THREADS_>>>(
        x, hx, wih, whh, bih, bhh, (const float4*)memory, (float4*)out_mem);
    // attention + remaining 30% of the copy, roles interleaved per wave
    fused_attn_k<<<B_TOTAL_BLOCKS_, 128>>>(
        cx, gi, memory, (const float4*)memory, (float4*)out_mem);
    // attention-output GEMM with fused LSTM epilogue + owner-cell scatter
    gemm_attn_final_k<<<B_ / 128, 256>>>(
        attn_w, attn_b, gi, memory, out_hy, out_c, out_mem);
}